// round 13
// baseline (speedup 1.0000x reference)
#include <cuda_runtime.h>
#include <cuda_fp16.h>

#define IMG      384
#define W_OUT    48          // 8 * 48 = 384 exact
#define LCOLS    60          // 48 + 6+6 halo
#define TILE_H   32          // output rows per block (two 16-row vertical slices)
#define SLICE_H  16
#define ROW_U2   (LCOLS * 4) // uint2 (half4) per smem row = 240 -> 1920 B
#define SMEM_BYTES (TILE_H * ROW_U2 * 8)   // 61440 B -> 2 blocks/SM = 122.9 KB

// Normalized 1D gaussian, sigma=2, ws=13 (literals -> imm-form FMA)
__device__ constexpr float GW[13] = {
    0.0022181959f, 0.0087731350f, 0.0270231560f, 0.0648251852f,
    0.1211093910f, 0.1762131227f, 0.1996756275f, 0.1762131227f,
    0.1211093910f, 0.0648251852f, 0.0270231560f, 0.0087731350f,
    0.0022181959f };

__device__ __forceinline__ float4 f4z() { return make_float4(0.f, 0.f, 0.f, 0.f); }

union H2U { __half2 h; unsigned u; };

// pack float4 -> 2x half2
__device__ __forceinline__ uint2 pack_h4(float4 v) {
    H2U a, b;
    a.h = __floats2half2_rn(v.x, v.y);
    b.h = __floats2half2_rn(v.z, v.w);
    uint2 r; r.x = a.u; r.y = b.u;
    return r;
}

__global__ __launch_bounds__(512, 2)
void gauss13_kernel(const float* __restrict__ in, float* __restrict__ out)
{
    // smem: [TILE_H rows][60 pixels][4 quads] of half4 (8 B). Full 16-ch pixel = 32 B.
    extern __shared__ uint2 sV[];

    const int n  = blockIdx.z;           // batch (full 16 channels per block)
    const int x0 = blockIdx.x * W_OUT;
    const int y0 = blockIdx.y * TILE_H;
    const int tid = threadIdx.x;

    const float4* __restrict__ ibase =
        reinterpret_cast<const float4*>(in) + (size_t)n * (IMG * IMG * 4);
    float4* __restrict__ obase =
        reinterpret_cast<float4*>(out) + (size_t)n * (IMG * IMG * 4);

    // ------------- vertical pass: packed fp16 ring + HFMA2 -> smem fp16 -------------
    // Two slices: tid[8] selects 16-row half; within a slice, thread = (col, q).
    // Warp lanes = 8 consecutive pixels x 4 quads -> 512 B contiguous per LDG.
    {
        const int s   = tid >> 8;          // slice 0 or 1
        const int t   = tid & 255;
        const int q   = t & 3;
        const int col = t >> 2;            // 0..63; only 0..59 active
        if (col < LCOLS) {
            const int gw  = x0 - 6 + col;
            const bool wok = ((unsigned)gw < (unsigned)IMG);
            const int r0  = y0 + s * SLICE_H - 6;
            const float4* cb = ibase + q;
            uint2* sp = sV + (s * SLICE_H) * ROW_U2 + col * 4 + q;

            uint2 win[13];                 // packed half4 ring (26 regs)
            #pragma unroll
            for (int i = 0; i < 12; ++i) {
                int h = r0 + i;
                win[i] = pack_h4((wok && (unsigned)h < (unsigned)IMG)
                       ? __ldg(cb + ((size_t)h * IMG + gw) * 4) : f4z());
            }
            #pragma unroll
            for (int r = 0; r < SLICE_H; ++r) {
                int h = r0 + 12 + r;
                win[(r + 12) % 13] = pack_h4((wok && (unsigned)h < (unsigned)IMG)
                       ? __ldg(cb + ((size_t)h * IMG + gw) * 4) : f4z());
                H2U a01, a23;
                a01.h = __float2half2_rn(0.f);
                a23.h = __float2half2_rn(0.f);
                #pragma unroll
                for (int k = 0; k < 13; ++k) {
                    const uint2 w = win[(r + k) % 13];
                    const __half2 wk2 = __float2half2_rn(GW[k]);  // folded const
                    H2U v0, v1; v0.u = w.x; v1.u = w.y;
                    a01.h = __hfma2(wk2, v0.h, a01.h);
                    a23.h = __hfma2(wk2, v1.h, a23.h);
                }
                uint2 pk; pk.x = a01.u; pk.y = a23.u;
                sp[r * ROW_U2] = pk;       // 128 B contiguous per 16-lane phase
            }
        }
    }
    __syncthreads();

    // ------------- horizontal pass (smem fp16 -> f32 accum -> global) ----------------
    // thread = (q, seg, row): 4*4*32 = 512 exactly. Warp stores 4 consecutive
    // full pixels x 2 rows -> coalesced.
    {
        const int q   = tid & 3;
        const int seg = (tid >> 2) & 3;
        const int row = tid >> 4;          // 0..31

        float4 acc[12];
        #pragma unroll
        for (int i = 0; i < 12; ++i) acc[i] = f4z();

        const uint2* rowp = sV + row * ROW_U2 + q;

        #pragma unroll
        for (int c = 0; c < 57; ++c) {     // c in [4i, 4i+12] for i = 0..11
            uint2 pk = rowp[(seg + c) * 4];
            H2U u0, u1; u0.u = pk.x; u1.u = pk.y;
            float2 f01 = __half22float2(u0.h);
            float2 f23 = __half22float2(u1.h);
            #pragma unroll
            for (int i = 0; i < 12; ++i) {
                const int k = c - 4 * i;
                if (k >= 0 && k < 13) {     // compile-time pruned
                    const float wk = GW[k]; // literal -> FFMA-imm
                    acc[i].x = fmaf(wk, f01.x, acc[i].x);
                    acc[i].y = fmaf(wk, f01.y, acc[i].y);
                    acc[i].z = fmaf(wk, f23.x, acc[i].z);
                    acc[i].w = fmaf(wk, f23.y, acc[i].w);
                }
            }
        }

        const int gy = y0 + row;
        float4* ob = obase + q;
        #pragma unroll
        for (int i = 0; i < 12; ++i) {
            const int gx = x0 + seg + 4 * i;   // always < 384
            ob[((size_t)gy * IMG + gx) * 4] = acc[i];
        }
    }
}

extern "C" void kernel_launch(void* const* d_in, const int* in_sizes, int n_in,
                              void* d_out, int out_size)
{
    (void)in_sizes; (void)n_in; (void)out_size;
    const float* x = (const float*)d_in[0];
    float* y = (float*)d_out;

    cudaFuncSetAttribute(gauss13_kernel,
                         cudaFuncAttributeMaxDynamicSharedMemorySize, SMEM_BYTES);

    dim3 grid(IMG / W_OUT /* 8 */, IMG / TILE_H /* 12 */, 32);
    dim3 block(512);
    gauss13_kernel<<<grid, block, SMEM_BYTES>>>(x, y);
}

// round 14
// speedup vs baseline: 1.0257x; 1.0257x over previous
#include <cuda_runtime.h>
#include <cuda_fp16.h>

#define IMG      384
#define W_OUT    48          // 8 * 48 = 384 exact
#define LCOLS    60          // 48 + 6+6 halo
#define TILE_H   16          // output rows per block
#define ROW_U2   (LCOLS * 4) // uint2 (half4) per smem row = 240 -> 1920 B
#define SMEM_BYTES (TILE_H * ROW_U2 * 8)   // 30720 B -> 5 blocks/SM = 153.6 KB

// Normalized 1D gaussian, sigma=2, ws=13 (literals -> imm-form FMA)
__device__ constexpr float GW[13] = {
    0.0022181959f, 0.0087731350f, 0.0270231560f, 0.0648251852f,
    0.1211093910f, 0.1762131227f, 0.1996756275f, 0.1762131227f,
    0.1211093910f, 0.0648251852f, 0.0270231560f, 0.0087731350f,
    0.0022181959f };

__device__ __forceinline__ float4 f4z() { return make_float4(0.f, 0.f, 0.f, 0.f); }

union H2U { __half2 h; unsigned u; };

// pack float4 -> 2x half2
__device__ __forceinline__ uint2 pack_h4(float4 v) {
    H2U a, b;
    a.h = __floats2half2_rn(v.x, v.y);
    b.h = __floats2half2_rn(v.z, v.w);
    uint2 r; r.x = a.u; r.y = b.u;
    return r;
}

__global__ __launch_bounds__(256, 5)
void gauss13_kernel(const float* __restrict__ in, float* __restrict__ out)
{
    // smem: [TILE_H rows][60 pixels][4 quads] of half4 (8 B). Full 16-ch pixel = 32 B.
    extern __shared__ uint2 sV[];

    const int n  = blockIdx.z;           // batch (full 16 channels per block)
    const int x0 = blockIdx.x * W_OUT;
    const int y0 = blockIdx.y * TILE_H;
    const int tid = threadIdx.x;

    const float4* __restrict__ ibase =
        reinterpret_cast<const float4*>(in) + (size_t)n * (IMG * IMG * 4);

    // ------------- vertical pass: packed fp16 ring + HFMA2 -> smem fp16 -------------
    // thread = (col 0..59, q 0..3); warp = 8 consecutive pixels -> 512 B per LDG.
    {
        const int q   = tid & 3;
        const int col = tid >> 2;          // 0..63; only 0..59 active
        if (col < LCOLS) {
            const int gw  = x0 - 6 + col;
            const bool wok = ((unsigned)gw < (unsigned)IMG);
            const int r0  = y0 - 6;
            const float4* cb = ibase + q;
            uint2* sp = sV + col * 4 + q;

            uint2 win[13];                 // packed half4 ring (26 regs)
            #pragma unroll
            for (int i = 0; i < 12; ++i) {
                int h = r0 + i;
                win[i] = pack_h4((wok && (unsigned)h < (unsigned)IMG)
                       ? __ldg(cb + ((size_t)h * IMG + gw) * 4) : f4z());
            }
            #pragma unroll
            for (int r = 0; r < TILE_H; ++r) {
                int h = r0 + 12 + r;
                win[(r + 12) % 13] = pack_h4((wok && (unsigned)h < (unsigned)IMG)
                       ? __ldg(cb + ((size_t)h * IMG + gw) * 4) : f4z());
                H2U a01, a23;
                a01.h = __float2half2_rn(0.f);
                a23.h = __float2half2_rn(0.f);
                #pragma unroll
                for (int k = 0; k < 13; ++k) {
                    const uint2 w = win[(r + k) % 13];
                    const __half2 wk2 = __float2half2_rn(GW[k]);  // folded const
                    H2U v0, v1; v0.u = w.x; v1.u = w.y;
                    a01.h = __hfma2(wk2, v0.h, a01.h);
                    a23.h = __hfma2(wk2, v1.h, a23.h);
                }
                uint2 pk; pk.x = a01.u; pk.y = a23.u;
                sp[r * ROW_U2] = pk;       // 128 B contiguous per 16-lane phase
            }
        }
    }
    __syncthreads();

    // ------------- horizontal pass: channel-split, float2 accumulators ---------------
    // thread = (cp 0..7, seg 0..3, rh 0..7); handles rows rh and rh+8.
    // Each thread owns 2 channels (one half2 word) of 12 output pixels.
    {
        const int cp  = tid & 7;           // channel pair (half2 / float2 index)
        const int seg = (tid >> 3) & 3;    // output col = seg + 4*i
        const int rh  = tid >> 5;          // 0..7

        const unsigned* sw = reinterpret_cast<const unsigned*>(sV);
        float2* ob2 = reinterpret_cast<float2*>(out) + (size_t)n * (IMG * IMG * 8) + cp;

        for (int pass = 0; pass < 2; ++pass) {
            const int row = rh + 8 * pass;

            float2 acc[12];
            #pragma unroll
            for (int i = 0; i < 12; ++i) acc[i] = make_float2(0.f, 0.f);

            // word index: row*480 + pixel*8 + cp  (uint granularity)
            const unsigned* rp = sw + row * (ROW_U2 * 2) + seg * 8 + cp;

            #pragma unroll
            for (int c = 0; c < 57; ++c) {     // pixel = seg + c
                H2U u; u.u = rp[c * 8];
                float2 f = __half22float2(u.h);
                #pragma unroll
                for (int i = 0; i < 12; ++i) {
                    const int k = c - 4 * i;
                    if (k >= 0 && k < 13) {     // compile-time pruned
                        const float wk = GW[k]; // literal -> FFMA-imm
                        acc[i].x = fmaf(wk, f.x, acc[i].x);
                        acc[i].y = fmaf(wk, f.y, acc[i].y);
                    }
                }
            }

            const int gy = y0 + row;
            #pragma unroll
            for (int i = 0; i < 12; ++i) {
                const int gx = x0 + seg + 4 * i;   // always < 384
                ob2[((size_t)gy * IMG + gx) * 8] = acc[i];
            }
        }
    }
}

extern "C" void kernel_launch(void* const* d_in, const int* in_sizes, int n_in,
                              void* d_out, int out_size)
{
    (void)in_sizes; (void)n_in; (void)out_size;
    const float* x = (const float*)d_in[0];
    float* y = (float*)d_out;

    cudaFuncSetAttribute(gauss13_kernel,
                         cudaFuncAttributeMaxDynamicSharedMemorySize, SMEM_BYTES);

    dim3 grid(IMG / W_OUT /* 8 */, IMG / TILE_H /* 24 */, 32);
    dim3 block(256);
    gauss13_kernel<<<grid, block, SMEM_BYTES>>>(x, y);
}

// round 15
// speedup vs baseline: 1.2066x; 1.1764x over previous
#include <cuda_runtime.h>
#include <cuda_fp16.h>

#define IMG      384
#define W_OUT    48          // 8 * 48 = 384 exact
#define LCOLS    60          // 48 + 6+6 halo
#define TILE_H   16          // output rows per block
#define NLOAD    (TILE_H + 12)  // 28 input rows per column
#define ROW_U2   (LCOLS * 4) // uint2 (half4) per smem row = 240 -> 1920 B
#define SMEM_BYTES (TILE_H * ROW_U2 * 8)   // 30720 B -> 4 blocks/SM

// Normalized 1D gaussian, sigma=2, ws=13 (literals -> imm-form FMA)
__device__ constexpr float GW[13] = {
    0.0022181959f, 0.0087731350f, 0.0270231560f, 0.0648251852f,
    0.1211093910f, 0.1762131227f, 0.1996756275f, 0.1762131227f,
    0.1211093910f, 0.0648251852f, 0.0270231560f, 0.0087731350f,
    0.0022181959f };

__device__ __forceinline__ float4 f4z() { return make_float4(0.f, 0.f, 0.f, 0.f); }

union H2U { __half2 h; unsigned u; };

// pack float4 -> 2x half2
__device__ __forceinline__ uint2 pack_h4(float4 v) {
    H2U a, b;
    a.h = __floats2half2_rn(v.x, v.y);
    b.h = __floats2half2_rn(v.z, v.w);
    uint2 r; r.x = a.u; r.y = b.u;
    return r;
}

__global__ __launch_bounds__(256, 4)
void gauss13_kernel(const float* __restrict__ in, float* __restrict__ out)
{
    // smem: [TILE_H rows][60 pixels][4 quads] of half4 (8 B). Full 16-ch pixel = 32 B.
    extern __shared__ uint2 sV[];

    const int n  = blockIdx.z;           // batch (full 16 channels per block)
    const int x0 = blockIdx.x * W_OUT;
    const int y0 = blockIdx.y * TILE_H;
    const int tid = threadIdx.x;

    const float4* __restrict__ ibase =
        reinterpret_cast<const float4*>(in) + (size_t)n * (IMG * IMG * 4);
    float4* __restrict__ obase =
        reinterpret_cast<float4*>(out) + (size_t)n * (IMG * IMG * 4);

    // ---- vertical pass: 16-slot packed ring, 3-deep prefetch, HFMA2 dual-tree ----
    {
        const int q   = tid & 3;
        const int col = tid >> 2;          // 0..63; only 0..59 active
        if (col < LCOLS) {
            const int gw  = x0 - 6 + col;
            const bool wok = ((unsigned)gw < (unsigned)IMG);
            const int r0  = y0 - 6;
            const float4* cb = ibase + q;
            uint2* sp = sV + col * 4 + q;

            // guarded row load
            auto ldrow = [&](int i) -> float4 {
                const int h = r0 + i;
                return (wok && (unsigned)h < (unsigned)IMG)
                     ? __ldg(cb + ((size_t)h * IMG + gw) * 4) : f4z();
            };

            uint2 win[16];                 // packed half4 ring (32 regs)
            #pragma unroll
            for (int i = 0; i < 14; ++i)
                win[i] = pack_h4(ldrow(i));
            float4 pf = ldrow(14);         // staged raw row

            #pragma unroll
            for (int r = 0; r < TILE_H; ++r) {
                // insert staged row r+14 into ring; refill stage with row r+15
                win[(r + 14) & 15] = pack_h4(pf);
                if (r + 15 < NLOAD)
                    pf = ldrow(r + 15);

                // dual-tree tap accumulation (chain depth ~7)
                H2U sA0, sA1, sB0, sB1;
                sA0.h = __float2half2_rn(0.f); sA1.h = __float2half2_rn(0.f);
                sB0.h = __float2half2_rn(0.f); sB1.h = __float2half2_rn(0.f);
                #pragma unroll
                for (int k = 0; k < 7; ++k) {
                    const uint2 w = win[(r + k) & 15];
                    const __half2 wk2 = __float2half2_rn(GW[k]);
                    H2U v0, v1; v0.u = w.x; v1.u = w.y;
                    sA0.h = __hfma2(wk2, v0.h, sA0.h);
                    sA1.h = __hfma2(wk2, v1.h, sA1.h);
                }
                #pragma unroll
                for (int k = 7; k < 13; ++k) {
                    const uint2 w = win[(r + k) & 15];
                    const __half2 wk2 = __float2half2_rn(GW[k]);
                    H2U v0, v1; v0.u = w.x; v1.u = w.y;
                    sB0.h = __hfma2(wk2, v0.h, sB0.h);
                    sB1.h = __hfma2(wk2, v1.h, sB1.h);
                }
                H2U a01, a23;
                a01.h = __hadd2(sA0.h, sB0.h);
                a23.h = __hadd2(sA1.h, sB1.h);
                uint2 pk; pk.x = a01.u; pk.y = a23.u;
                sp[r * ROW_U2] = pk;       // 128 B contiguous per 16-lane phase
            }
        }
    }
    __syncthreads();

    // ------------- horizontal pass (smem fp16 -> f32 accum -> global) ----------------
    // thread = (q, seg, row): warp stores 4 consecutive full pixels x 2 rows.
    {
        const int q   = tid & 3;
        const int seg = (tid >> 2) & 3;
        const int row = tid >> 4;          // 0..15

        float4 acc[12];
        #pragma unroll
        for (int i = 0; i < 12; ++i) acc[i] = f4z();

        const uint2* rowp = sV + row * ROW_U2 + q;

        #pragma unroll
        for (int c = 0; c < 57; ++c) {     // c in [4i, 4i+12] for i = 0..11
            uint2 pk = rowp[(seg + c) * 4];
            H2U u0, u1; u0.u = pk.x; u1.u = pk.y;
            float2 f01 = __half22float2(u0.h);
            float2 f23 = __half22float2(u1.h);
            #pragma unroll
            for (int i = 0; i < 12; ++i) {
                const int k = c - 4 * i;
                if (k >= 0 && k < 13) {     // compile-time pruned
                    const float wk = GW[k]; // literal -> FFMA-imm
                    acc[i].x = fmaf(wk, f01.x, acc[i].x);
                    acc[i].y = fmaf(wk, f01.y, acc[i].y);
                    acc[i].z = fmaf(wk, f23.x, acc[i].z);
                    acc[i].w = fmaf(wk, f23.y, acc[i].w);
                }
            }
        }

        const int gy = y0 + row;
        float4* ob = obase + q;
        #pragma unroll
        for (int i = 0; i < 12; ++i) {
            const int gx = x0 + seg + 4 * i;   // always < 384
            ob[((size_t)gy * IMG + gx) * 4] = acc[i];
        }
    }
}

extern "C" void kernel_launch(void* const* d_in, const int* in_sizes, int n_in,
                              void* d_out, int out_size)
{
    (void)in_sizes; (void)n_in; (void)out_size;
    const float* x = (const float*)d_in[0];
    float* y = (float*)d_out;

    cudaFuncSetAttribute(gauss13_kernel,
                         cudaFuncAttributeMaxDynamicSharedMemorySize, SMEM_BYTES);

    dim3 grid(IMG / W_OUT /* 8 */, IMG / TILE_H /* 24 */, 32);
    dim3 block(256);
    gauss13_kernel<<<grid, block, SMEM_BYTES>>>(x, y);
}